// round 9
// baseline (speedup 1.0000x reference)
#include <cuda_runtime.h>
#include <cuda_bf16.h>
#include <cstdint>
#include <cstddef>

// ============================================================================
// out[4096,4096](fp32, bf16-valued) = X[4096,4096](bf16) @ W[4096,4096]^T
// Base-sm_103 path: mma.sync.m16n8k16.bf16 + cp.async 3-stage pipeline.
// Padded smem layout (stride 144 B) — no swizzle anywhere.
// NOTE: harness output dtype is float32 (numpy has no bf16); values are the
// bf16-rounded results upcast exactly.
// ============================================================================
#define MDIM 4096
#define NDIM 4096
#define KDIM 4096

#define BM 128
#define BN 256
#define BK 64                 // 64 bf16 = 128 B of K per stage row
#define STAGES 3
#define THREADS 256

#define AST 144               // padded row stride in bytes (128 data + 16 pad)
#define A_STAGE (BM * AST)                    // 18432 B
#define B_STAGE (BN * AST)                    // 36864 B
#define STAGE_BYTES (A_STAGE + B_STAGE)       // 55296 B
#define SMEM_BYTES (STAGES * STAGE_BYTES + 256)

#define NUM_K_ITERS (KDIM / BK)   // 64
#define NUM_M_TILES (MDIM / BM)   // 32
#define NUM_N_TILES (NDIM / BN)   // 16

// bf16 scratch (device globals — no allocations anywhere)
__device__ __nv_bfloat16 g_xb[(size_t)MDIM * KDIM];
__device__ __nv_bfloat16 g_wb[(size_t)NDIM * KDIM];

// ============================================================================
// PTX helpers (sm_80-era features only; valid on base .target sm_103)
// ============================================================================
__device__ __forceinline__ uint32_t smem_u32(const void* p) {
    uint32_t a;
    asm("{ .reg .u64 t; cvta.to.shared.u64 t, %1; cvt.u32.u64 %0, t; }"
        : "=r"(a) : "l"(p));
    return a;
}

__device__ __forceinline__ void cp_async16(uint32_t dst, const void* src) {
    asm volatile("cp.async.cg.shared.global [%0], [%1], 16;"
                 :: "r"(dst), "l"(src) : "memory");
}

__device__ __forceinline__ void cp_commit() {
    asm volatile("cp.async.commit_group;" ::: "memory");
}

template <int N>
__device__ __forceinline__ void cp_wait() {
    asm volatile("cp.async.wait_group %0;" :: "n"(N) : "memory");
}

__device__ __forceinline__ void ldsm_x4(uint32_t& r0, uint32_t& r1,
                                        uint32_t& r2, uint32_t& r3,
                                        uint32_t addr) {
    asm volatile("ldmatrix.sync.aligned.m8n8.x4.shared.b16 {%0,%1,%2,%3}, [%4];"
                 : "=r"(r0), "=r"(r1), "=r"(r2), "=r"(r3) : "r"(addr));
}

__device__ __forceinline__ void mma16816(float* c, const uint32_t* a,
                                         uint32_t b0, uint32_t b1) {
    asm volatile(
        "mma.sync.aligned.m16n8k16.row.col.f32.bf16.bf16.f32 "
        "{%0,%1,%2,%3}, {%4,%5,%6,%7}, {%8,%9}, {%0,%1,%2,%3};"
        : "+f"(c[0]), "+f"(c[1]), "+f"(c[2]), "+f"(c[3])
        : "r"(a[0]), "r"(a[1]), "r"(a[2]), "r"(a[3]), "r"(b0), "r"(b1));
}

__device__ __forceinline__ unsigned pack2(__nv_bfloat16 lo, __nv_bfloat16 hi) {
    return (unsigned)__bfloat16_as_ushort(lo) |
           ((unsigned)__bfloat16_as_ushort(hi) << 16);
}

// ============================================================================
// Convert kernels: fp32 -> bf16 scratch (X cast; W dequant in bf16 exactly
// matching jnp: bf16(w_fp8) * bf16(scale))
// ============================================================================
__global__ __launch_bounds__(256) void cvt_x_kernel(const float* __restrict__ x) {
    size_t i = (size_t)blockIdx.x * blockDim.x + threadIdx.x;   // 8 floats each
    const float4* p = reinterpret_cast<const float4*>(x) + i * 2;
    float4 a = p[0], b = p[1];
    uint4 o;
    o.x = pack2(__float2bfloat16_rn(a.x), __float2bfloat16_rn(a.y));
    o.y = pack2(__float2bfloat16_rn(a.z), __float2bfloat16_rn(a.w));
    o.z = pack2(__float2bfloat16_rn(b.x), __float2bfloat16_rn(b.y));
    o.w = pack2(__float2bfloat16_rn(b.z), __float2bfloat16_rn(b.w));
    reinterpret_cast<uint4*>(g_xb)[i] = o;
}

__global__ __launch_bounds__(256) void cvt_w_kernel(const float* __restrict__ w,
                                                    const float* __restrict__ scale) {
    size_t i = (size_t)blockIdx.x * blockDim.x + threadIdx.x;   // 8 floats each
    int row = (int)(i >> 9);                                    // (i*8)/4096
    __nv_bfloat16 sb = __float2bfloat16_rn(scale[row]);
    const float4* p = reinterpret_cast<const float4*>(w) + i * 2;
    float4 a = p[0], b = p[1];
    float f[8] = {a.x, a.y, a.z, a.w, b.x, b.y, b.z, b.w};
    unsigned u[4];
#pragma unroll
    for (int j = 0; j < 4; j++) {
        __nv_bfloat16 lo = __hmul(__float2bfloat16_rn(f[2 * j]), sb);
        __nv_bfloat16 hi = __hmul(__float2bfloat16_rn(f[2 * j + 1]), sb);
        u[j] = pack2(lo, hi);
    }
    reinterpret_cast<uint4*>(g_wb)[i] = make_uint4(u[0], u[1], u[2], u[3]);
}

// ============================================================================
// GEMM: 128x256x64 CTA tile, 8 warps @ 64x64, 3-stage cp.async pipeline
// ============================================================================
__global__ __launch_bounds__(THREADS, 1) void gemm_kernel(
    float* __restrict__ out, const float* __restrict__ bias) {
    extern __shared__ char smem[];
    const uint32_t base = (smem_u32(smem) + 127u) & ~127u;

    const int tid = threadIdx.x;
    const int lane = tid & 31;
    const int wid = tid >> 5;
    const int wm0 = (wid & 1) * 64;    // warp M offset within CTA tile
    const int wn0 = (wid >> 1) * 64;   // warp N offset within CTA tile

    const int bid = blockIdx.x;
    const int tm = bid & (NUM_M_TILES - 1);  // consecutive bids share B panel
    const int tn = bid >> 5;
    const int m0 = tm * BM;
    const int n0 = tn * BN;

    const __nv_bfloat16* Ag = g_xb + (size_t)m0 * KDIM;
    const __nv_bfloat16* Bg = g_wb + (size_t)n0 * KDIM;

    // cp.async coordinates: each thread moves one 16B chunk per (row-group)
    const int ld_r = tid >> 3;        // 0..31  (row within group of 32)
    const int ld_c = tid & 7;         // 0..7   (16B chunk within 128B of K)

    auto load_stage = [&](int kit, int s) {
        if (kit < NUM_K_ITERS) {
            const uint32_t sa = base + s * STAGE_BYTES;
            const uint32_t sb = sa + A_STAGE;
            const __nv_bfloat16* ak = Ag + kit * BK + ld_c * 8;
            const __nv_bfloat16* bk = Bg + kit * BK + ld_c * 8;
#pragma unroll
            for (int it = 0; it < 4; it++) {       // A: 128 rows
                int r = ld_r + it * 32;
                cp_async16(sa + r * AST + ld_c * 16, ak + (size_t)r * KDIM);
            }
#pragma unroll
            for (int it = 0; it < 8; it++) {       // B: 256 rows
                int r = ld_r + it * 32;
                cp_async16(sb + r * AST + ld_c * 16, bk + (size_t)r * KDIM);
            }
        }
        cp_commit();
    };

    // ldmatrix x4 addressing (PTX spec): lane 8i+j supplies row j of matrix i.
    //   matrices 0/1 = rows 0-7 / 8-15 of the 16-row fragment, k bytes +0
    //   matrices 2/3 = rows 0-7 / 8-15,                        k bytes +16
    const int g = lane >> 3;                        // matrix index 0..3
    const int j = lane & 7;                         // row within matrix
    const int frag_row = (g & 1) * 8 + j;           // 0..15
    const int frag_kb  = (g >> 1) * 16;             // 0 or 16 bytes

    float acc[4][8][4];
#pragma unroll
    for (int i = 0; i < 4; i++)
#pragma unroll
        for (int n = 0; n < 8; n++)
#pragma unroll
            for (int e = 0; e < 4; e++) acc[i][n][e] = 0.0f;

    // Prologue: fill STAGES-1 stages
    load_stage(0, 0);
    load_stage(1, 1);

    for (int kit = 0; kit < NUM_K_ITERS; kit++) {
        const int s = kit % STAGES;
        cp_wait<1>();          // stage kit's group complete (per-thread)
        __syncthreads();       // make all threads' stage-kit data visible

        // Prefetch stage kit+2 into the slot consumed at iteration kit-1
        load_stage(kit + 2, (kit + 2) % STAGES);

        const uint32_t sa = base + s * STAGE_BYTES;
        const uint32_t sb = sa + A_STAGE;

#pragma unroll
        for (int q = 0; q < 4; q++) {              // 4 x K16 per BK=64 stage
            uint32_t a[4][4];
#pragma unroll
            for (int mi = 0; mi < 4; mi++) {
                uint32_t addr = sa + (wm0 + mi * 16 + frag_row) * AST +
                                q * 32 + frag_kb;
                ldsm_x4(a[mi][0], a[mi][1], a[mi][2], a[mi][3], addr);
            }
#pragma unroll
            for (int p = 0; p < 4; p++) {          // each p = 16 n-cols
                uint32_t b0, b1, b2, b3;           // (n0-7,kLo)(n8-15,kLo)
                uint32_t addr = sb + (wn0 + p * 16 + frag_row) * AST +
                                q * 32 + frag_kb;  // (n0-7,kHi)(n8-15,kHi)
                ldsm_x4(b0, b1, b2, b3, addr);
#pragma unroll
                for (int mi = 0; mi < 4; mi++) {
                    mma16816(acc[mi][2 * p],     a[mi], b0, b2);
                    mma16816(acc[mi][2 * p + 1], a[mi], b1, b3);
                }
            }
        }
        __syncthreads();
    }

    // Epilogue: value = bf16(fp32 accum) + bf16 bias (reference rounding),
    // stored as fp32 (harness output dtype is float32; bf16 exact in fp32).
#pragma unroll
    for (int mi = 0; mi < 4; mi++) {
        int r0 = m0 + wm0 + mi * 16 + (lane >> 2);
        float* p0 = out + (size_t)r0 * NDIM;
        float* p1 = p0 + (size_t)8 * NDIM;
#pragma unroll
        for (int nj = 0; nj < 8; nj++) {
            int col = n0 + wn0 + nj * 8 + (lane & 3) * 2;
            __nv_bfloat16 b0 = __float2bfloat16_rn(bias[col]);
            __nv_bfloat16 b1 = __float2bfloat16_rn(bias[col + 1]);
            float2 v0, v1;
            v0.x = __bfloat162float(__hadd(__float2bfloat16_rn(acc[mi][nj][0]), b0));
            v0.y = __bfloat162float(__hadd(__float2bfloat16_rn(acc[mi][nj][1]), b1));
            v1.x = __bfloat162float(__hadd(__float2bfloat16_rn(acc[mi][nj][2]), b0));
            v1.y = __bfloat162float(__hadd(__float2bfloat16_rn(acc[mi][nj][3]), b1));
            *reinterpret_cast<float2*>(p0 + col) = v0;
            *reinterpret_cast<float2*>(p1 + col) = v1;
        }
    }
}

// ============================================================================
// Launch
// ============================================================================
extern "C" void kernel_launch(void* const* d_in, const int* in_sizes, int n_in,
                              void* d_out, int out_size) {
    const float* x     = (const float*)d_in[0];   // [2,2048,4096] fp32
    const float* wq    = (const float*)d_in[1];   // [4096,4096] fp32 (fp8 vals)
    const float* wscal = (const float*)d_in[2];   // [4096,1] fp32
    const float* bias  = (const float*)d_in[3];   // [4096] fp32
    float* out         = (float*)d_out;           // [2,2048,4096] fp32

    cudaFuncSetAttribute(gemm_kernel,
                         cudaFuncAttributeMaxDynamicSharedMemorySize,
                         SMEM_BYTES);

    cvt_x_kernel<<<8192, 256>>>(x);
    cvt_w_kernel<<<8192, 256>>>(wq, wscal);
    gemm_kernel<<<NUM_M_TILES * NUM_N_TILES, THREADS, SMEM_BYTES>>>(out, bias);
}

// round 11
// speedup vs baseline: 1.0278x; 1.0278x over previous
#include <cuda_runtime.h>
#include <cuda_bf16.h>
#include <cstdint>
#include <cstddef>

// ============================================================================
// out[4096,4096](fp32, bf16-valued) = X[4096,4096](bf16) @ W[4096,4096]^T
// mma.sync.m16n8k16.bf16 + 4-stage cp.async pipeline, 1 barrier per stage,
// register double-buffered fragments. Padded smem (144 B stride, no swizzle).
// ============================================================================
#define MDIM 4096
#define NDIM 4096
#define KDIM 4096

#define BM 128
#define BN 256
#define BK 64                 // 64 bf16 = 128 B of K per stage row
#define STAGES 4
#define THREADS 256

#define AST 144               // padded row stride (128 data + 16 pad)
#define A_STAGE (BM * AST)                    // 18432 B
#define B_STAGE (BN * AST)                    // 36864 B
#define STAGE_BYTES (A_STAGE + B_STAGE)       // 55296 B
#define SMEM_BYTES (STAGES * STAGE_BYTES + 256)   // ~221.4 KB

#define NUM_K_ITERS (KDIM / BK)   // 64
#define NUM_M_TILES (MDIM / BM)   // 32
#define NUM_N_TILES (NDIM / BN)   // 16

__device__ __nv_bfloat16 g_xb[(size_t)MDIM * KDIM];
__device__ __nv_bfloat16 g_wb[(size_t)NDIM * KDIM];

// ============================================================================
// PTX helpers
// ============================================================================
__device__ __forceinline__ uint32_t smem_u32(const void* p) {
    uint32_t a;
    asm("{ .reg .u64 t; cvta.to.shared.u64 t, %1; cvt.u32.u64 %0, t; }"
        : "=r"(a) : "l"(p));
    return a;
}

__device__ __forceinline__ void cp_async16(uint32_t dst, const void* src) {
    asm volatile("cp.async.cg.shared.global [%0], [%1], 16;"
                 :: "r"(dst), "l"(src) : "memory");
}

__device__ __forceinline__ void cp_commit() {
    asm volatile("cp.async.commit_group;" ::: "memory");
}

template <int N>
__device__ __forceinline__ void cp_wait() {
    asm volatile("cp.async.wait_group %0;" :: "n"(N) : "memory");
}

__device__ __forceinline__ void ldsm_x4(uint32_t& r0, uint32_t& r1,
                                        uint32_t& r2, uint32_t& r3,
                                        uint32_t addr) {
    asm volatile("ldmatrix.sync.aligned.m8n8.x4.shared.b16 {%0,%1,%2,%3}, [%4];"
                 : "=r"(r0), "=r"(r1), "=r"(r2), "=r"(r3) : "r"(addr));
}

__device__ __forceinline__ void mma16816(float* c, const uint32_t* a,
                                         uint32_t b0, uint32_t b1) {
    asm volatile(
        "mma.sync.aligned.m16n8k16.row.col.f32.bf16.bf16.f32 "
        "{%0,%1,%2,%3}, {%4,%5,%6,%7}, {%8,%9}, {%0,%1,%2,%3};"
        : "+f"(c[0]), "+f"(c[1]), "+f"(c[2]), "+f"(c[3])
        : "r"(a[0]), "r"(a[1]), "r"(a[2]), "r"(a[3]), "r"(b0), "r"(b1));
}

__device__ __forceinline__ unsigned pack2(__nv_bfloat16 lo, __nv_bfloat16 hi) {
    return (unsigned)__bfloat16_as_ushort(lo) |
           ((unsigned)__bfloat16_as_ushort(hi) << 16);
}

// ============================================================================
// Fused convert: blocks [0,8192) cast X; [8192,16384) dequant W (bf16 math,
// matching jnp bf16(w_fp8) * bf16(scale) exactly)
// ============================================================================
__global__ __launch_bounds__(256) void cvt_kernel(const float* __restrict__ x,
                                                  const float* __restrict__ w,
                                                  const float* __restrict__ scale) {
    if (blockIdx.x < 8192) {
        size_t i = (size_t)blockIdx.x * 256 + threadIdx.x;      // 8 floats
        const float4* p = reinterpret_cast<const float4*>(x) + i * 2;
        float4 a = p[0], b = p[1];
        uint4 o;
        o.x = pack2(__float2bfloat16_rn(a.x), __float2bfloat16_rn(a.y));
        o.y = pack2(__float2bfloat16_rn(a.z), __float2bfloat16_rn(a.w));
        o.z = pack2(__float2bfloat16_rn(b.x), __float2bfloat16_rn(b.y));
        o.w = pack2(__float2bfloat16_rn(b.z), __float2bfloat16_rn(b.w));
        reinterpret_cast<uint4*>(g_xb)[i] = o;
    } else {
        size_t i = (size_t)(blockIdx.x - 8192) * 256 + threadIdx.x;
        int row = (int)(i >> 9);
        __nv_bfloat16 sb = __float2bfloat16_rn(scale[row]);
        const float4* p = reinterpret_cast<const float4*>(w) + i * 2;
        float4 a = p[0], b = p[1];
        float f[8] = {a.x, a.y, a.z, a.w, b.x, b.y, b.z, b.w};
        unsigned u[4];
#pragma unroll
        for (int j = 0; j < 4; j++) {
            __nv_bfloat16 lo = __hmul(__float2bfloat16_rn(f[2 * j]), sb);
            __nv_bfloat16 hi = __hmul(__float2bfloat16_rn(f[2 * j + 1]), sb);
            u[j] = pack2(lo, hi);
        }
        reinterpret_cast<uint4*>(g_wb)[i] = make_uint4(u[0], u[1], u[2], u[3]);
    }
}

// ============================================================================
// GEMM: 128x256x64 CTA tile, 8 warps @ 64x64, 4-stage pipeline, 1 bar/stage
// ============================================================================
__global__ __launch_bounds__(THREADS, 1) void gemm_kernel(
    float* __restrict__ out, const float* __restrict__ bias) {
    extern __shared__ char smem[];
    const uint32_t base = (smem_u32(smem) + 127u) & ~127u;

    const int tid = threadIdx.x;
    const int lane = tid & 31;
    const int wid = tid >> 5;
    const int wm0 = (wid & 1) * 64;
    const int wn0 = (wid >> 1) * 64;

    const int bid = blockIdx.x;
    const int tm = bid & (NUM_M_TILES - 1);  // consecutive bids share B panel
    const int tn = bid >> 5;
    const int m0 = tm * BM;
    const int n0 = tn * BN;

    const __nv_bfloat16* Ag = g_xb + (size_t)m0 * KDIM;
    const __nv_bfloat16* Bg = g_wb + (size_t)n0 * KDIM;

    const int ld_r = tid >> 3;        // 0..31
    const int ld_c = tid & 7;         // 0..7

    auto load_stage = [&](int kit, int s) {
        if (kit < NUM_K_ITERS) {
            const uint32_t sa = base + s * STAGE_BYTES;
            const uint32_t sb = sa + A_STAGE;
            const __nv_bfloat16* ak = Ag + kit * BK + ld_c * 8;
            const __nv_bfloat16* bk = Bg + kit * BK + ld_c * 8;
#pragma unroll
            for (int it = 0; it < 4; it++) {       // A: 128 rows
                int r = ld_r + it * 32;
                cp_async16(sa + r * AST + ld_c * 16, ak + (size_t)r * KDIM);
            }
#pragma unroll
            for (int it = 0; it < 8; it++) {       // B: 256 rows
                int r = ld_r + it * 32;
                cp_async16(sb + r * AST + ld_c * 16, bk + (size_t)r * KDIM);
            }
        }
        cp_commit();
    };

    // ldmatrix x4: lane 8i+j supplies row j of matrix i.
    const int g = lane >> 3;
    const int j = lane & 7;
    const int frag_row = (g & 1) * 8 + j;           // 0..15
    const int frag_kb  = (g >> 1) * 16;             // 0 or 16 bytes

    // Per-warp constant parts of ldsm addresses
    const uint32_t a_off0 = (uint32_t)((wm0 + frag_row) * AST + frag_kb);
    const uint32_t b_off0 = (uint32_t)((wn0 + frag_row) * AST + frag_kb);

    float acc[4][8][4];
#pragma unroll
    for (int i = 0; i < 4; i++)
#pragma unroll
        for (int n = 0; n < 8; n++)
#pragma unroll
            for (int e = 0; e < 4; e++) acc[i][n][e] = 0.0f;

    // Prologue: fill 3 of 4 stages (prefetch distance 3)
    load_stage(0, 0);
    load_stage(1, 1);
    load_stage(2, 2);

    uint32_t afr[2][4][4];   // [buf][mi][reg]
    uint32_t bfr[2][4][4];   // [buf][p][reg]

    for (int kit = 0; kit < NUM_K_ITERS; kit++) {
        const int s = kit & (STAGES - 1);
        cp_wait<2>();          // stage kit's group complete
        __syncthreads();       // single barrier per stage

        // Prefetch stage kit+3 into slot (kit+3)%4 = (kit-1)%4, whose reads
        // finished before this barrier.
        load_stage(kit + 3, (kit + 3) & (STAGES - 1));

        const uint32_t sa = base + s * STAGE_BYTES;
        const uint32_t sb = sa + A_STAGE;

        // Preload q=0 fragments into buffer 0
#pragma unroll
        for (int mi = 0; mi < 4; mi++)
            ldsm_x4(afr[0][mi][0], afr[0][mi][1], afr[0][mi][2], afr[0][mi][3],
                    sa + a_off0 + mi * 16 * AST);
#pragma unroll
        for (int p = 0; p < 4; p++)
            ldsm_x4(bfr[0][p][0], bfr[0][p][1], bfr[0][p][2], bfr[0][p][3],
                    sb + b_off0 + p * 16 * AST);

#pragma unroll
        for (int q = 0; q < 4; q++) {              // 4 x K16 per BK=64 stage
            const int cur = q & 1, nxt = cur ^ 1;
            if (q < 3) {                           // prefetch q+1 fragments
                const uint32_t kb = (uint32_t)((q + 1) * 32);
#pragma unroll
                for (int mi = 0; mi < 4; mi++)
                    ldsm_x4(afr[nxt][mi][0], afr[nxt][mi][1],
                            afr[nxt][mi][2], afr[nxt][mi][3],
                            sa + a_off0 + mi * 16 * AST + kb);
#pragma unroll
                for (int p = 0; p < 4; p++)
                    ldsm_x4(bfr[nxt][p][0], bfr[nxt][p][1],
                            bfr[nxt][p][2], bfr[nxt][p][3],
                            sb + b_off0 + p * 16 * AST + kb);
            }
#pragma unroll
            for (int p = 0; p < 4; p++)
#pragma unroll
                for (int mi = 0; mi < 4; mi++) {
                    mma16816(acc[mi][2 * p],     afr[cur][mi],
                             bfr[cur][p][0], bfr[cur][p][2]);
                    mma16816(acc[mi][2 * p + 1], afr[cur][mi],
                             bfr[cur][p][1], bfr[cur][p][3]);
                }
        }
    }

    // Epilogue: value = bf16(fp32 accum) + bf16 bias, stored as fp32
#pragma unroll
    for (int mi = 0; mi < 4; mi++) {
        int r0 = m0 + wm0 + mi * 16 + (lane >> 2);
        float* p0 = out + (size_t)r0 * NDIM;
        float* p1 = p0 + (size_t)8 * NDIM;
#pragma unroll
        for (int nj = 0; nj < 8; nj++) {
            int col = n0 + wn0 + nj * 8 + (lane & 3) * 2;
            __nv_bfloat16 b0 = __float2bfloat16_rn(bias[col]);
            __nv_bfloat16 b1 = __float2bfloat16_rn(bias[col + 1]);
            float2 v0, v1;
            v0.x = __bfloat162float(__hadd(__float2bfloat16_rn(acc[mi][nj][0]), b0));
            v0.y = __bfloat162float(__hadd(__float2bfloat16_rn(acc[mi][nj][1]), b1));
            v1.x = __bfloat162float(__hadd(__float2bfloat16_rn(acc[mi][nj][2]), b0));
            v1.y = __bfloat162float(__hadd(__float2bfloat16_rn(acc[mi][nj][3]), b1));
            *reinterpret_cast<float2*>(p0 + col) = v0;
            *reinterpret_cast<float2*>(p1 + col) = v1;
        }
    }
}

// ============================================================================
// Launch
// ============================================================================
extern "C" void kernel_launch(void* const* d_in, const int* in_sizes, int n_in,
                              void* d_out, int out_size) {
    const float* x     = (const float*)d_in[0];
    const float* wq    = (const float*)d_in[1];
    const float* wscal = (const float*)d_in[2];
    const float* bias  = (const float*)d_in[3];
    float* out         = (float*)d_out;

    cudaFuncSetAttribute(gemm_kernel,
                         cudaFuncAttributeMaxDynamicSharedMemorySize,
                         SMEM_BYTES);

    cvt_kernel<<<16384, 256>>>(x, wq, wscal);
    gemm_kernel<<<NUM_M_TILES * NUM_N_TILES, THREADS, SMEM_BYTES>>>(out, bias);
}

// round 12
// speedup vs baseline: 1.0654x; 1.0366x over previous
#include <cuda_runtime.h>
#include <cuda_bf16.h>
#include <cstdint>
#include <cstddef>

// ============================================================================
// out[4096,4096](fp32, bf16-valued) = X[4096,4096](bf16) @ W[4096,4096]^T
// mma.sync.m16n8k16.bf16, 4-stage cp.async pipeline, 512 threads (16 warps,
// 4/SMSP for latency coverage), warp tile 32x64. Padded smem, no swizzle.
// ============================================================================
#define MDIM 4096
#define NDIM 4096
#define KDIM 4096

#define BM 128
#define BN 256
#define BK 64                 // 64 bf16 = 128 B of K per stage row
#define STAGES 4
#define THREADS 512

#define AST 144               // padded row stride (128 data + 16 pad)
#define A_STAGE (BM * AST)                    // 18432 B
#define B_STAGE (BN * AST)                    // 36864 B
#define STAGE_BYTES (A_STAGE + B_STAGE)       // 55296 B
#define SMEM_BYTES (STAGES * STAGE_BYTES + 256)   // ~221.4 KB

#define NUM_K_ITERS (KDIM / BK)   // 64
#define NUM_M_TILES (MDIM / BM)   // 32
#define NUM_N_TILES (NDIM / BN)   // 16

__device__ __nv_bfloat16 g_xb[(size_t)MDIM * KDIM];
__device__ __nv_bfloat16 g_wb[(size_t)NDIM * KDIM];

// ============================================================================
// PTX helpers
// ============================================================================
__device__ __forceinline__ uint32_t smem_u32(const void* p) {
    uint32_t a;
    asm("{ .reg .u64 t; cvta.to.shared.u64 t, %1; cvt.u32.u64 %0, t; }"
        : "=r"(a) : "l"(p));
    return a;
}

__device__ __forceinline__ void cp_async16(uint32_t dst, const void* src) {
    asm volatile("cp.async.cg.shared.global [%0], [%1], 16;"
                 :: "r"(dst), "l"(src) : "memory");
}

__device__ __forceinline__ void cp_commit() {
    asm volatile("cp.async.commit_group;" ::: "memory");
}

template <int N>
__device__ __forceinline__ void cp_wait() {
    asm volatile("cp.async.wait_group %0;" :: "n"(N) : "memory");
}

__device__ __forceinline__ void ldsm_x4(uint32_t& r0, uint32_t& r1,
                                        uint32_t& r2, uint32_t& r3,
                                        uint32_t addr) {
    asm volatile("ldmatrix.sync.aligned.m8n8.x4.shared.b16 {%0,%1,%2,%3}, [%4];"
                 : "=r"(r0), "=r"(r1), "=r"(r2), "=r"(r3) : "r"(addr));
}

__device__ __forceinline__ void mma16816(float* c, const uint32_t* a,
                                         uint32_t b0, uint32_t b1) {
    asm volatile(
        "mma.sync.aligned.m16n8k16.row.col.f32.bf16.bf16.f32 "
        "{%0,%1,%2,%3}, {%4,%5,%6,%7}, {%8,%9}, {%0,%1,%2,%3};"
        : "+f"(c[0]), "+f"(c[1]), "+f"(c[2]), "+f"(c[3])
        : "r"(a[0]), "r"(a[1]), "r"(a[2]), "r"(a[3]), "r"(b0), "r"(b1));
}

__device__ __forceinline__ unsigned pack2(__nv_bfloat16 lo, __nv_bfloat16 hi) {
    return (unsigned)__bfloat16_as_ushort(lo) |
           ((unsigned)__bfloat16_as_ushort(hi) << 16);
}

// ============================================================================
// Fused convert: blocks [0,8192) cast X; [8192,16384) dequant W (bf16 math)
// ============================================================================
__global__ __launch_bounds__(256) void cvt_kernel(const float* __restrict__ x,
                                                  const float* __restrict__ w,
                                                  const float* __restrict__ scale) {
    if (blockIdx.x < 8192) {
        size_t i = (size_t)blockIdx.x * 256 + threadIdx.x;      // 8 floats
        const float4* p = reinterpret_cast<const float4*>(x) + i * 2;
        float4 a = p[0], b = p[1];
        uint4 o;
        o.x = pack2(__float2bfloat16_rn(a.x), __float2bfloat16_rn(a.y));
        o.y = pack2(__float2bfloat16_rn(a.z), __float2bfloat16_rn(a.w));
        o.z = pack2(__float2bfloat16_rn(b.x), __float2bfloat16_rn(b.y));
        o.w = pack2(__float2bfloat16_rn(b.z), __float2bfloat16_rn(b.w));
        reinterpret_cast<uint4*>(g_xb)[i] = o;
    } else {
        size_t i = (size_t)(blockIdx.x - 8192) * 256 + threadIdx.x;
        int row = (int)(i >> 9);
        __nv_bfloat16 sb = __float2bfloat16_rn(scale[row]);
        const float4* p = reinterpret_cast<const float4*>(w) + i * 2;
        float4 a = p[0], b = p[1];
        float f[8] = {a.x, a.y, a.z, a.w, b.x, b.y, b.z, b.w};
        unsigned u[4];
#pragma unroll
        for (int j = 0; j < 4; j++) {
            __nv_bfloat16 lo = __hmul(__float2bfloat16_rn(f[2 * j]), sb);
            __nv_bfloat16 hi = __hmul(__float2bfloat16_rn(f[2 * j + 1]), sb);
            u[j] = pack2(lo, hi);
        }
        reinterpret_cast<uint4*>(g_wb)[i] = make_uint4(u[0], u[1], u[2], u[3]);
    }
}

// ============================================================================
// GEMM: 128x256x64 CTA tile, 16 warps @ 32x64, 4-stage pipeline
// ============================================================================
__global__ __launch_bounds__(THREADS, 1) void gemm_kernel(
    float* __restrict__ out, const float* __restrict__ bias) {
    extern __shared__ char smem[];
    const uint32_t base = (smem_u32(smem) + 127u) & ~127u;

    const int tid = threadIdx.x;
    const int lane = tid & 31;
    const int wid = tid >> 5;
    const int wm0 = (wid & 3) * 32;    // 4 warp rows  * 32 = 128
    const int wn0 = (wid >> 2) * 64;   // 4 warp cols  * 64 = 256

    const int bid = blockIdx.x;
    const int tm = bid & (NUM_M_TILES - 1);  // consecutive bids share B panel
    const int tn = bid >> 5;
    const int m0 = tm * BM;
    const int n0 = tn * BN;

    const __nv_bfloat16* Ag = g_xb + (size_t)m0 * KDIM;
    const __nv_bfloat16* Bg = g_wb + (size_t)n0 * KDIM;

    // cp.async: 512 threads, 8 chunks (16B) per 128B row
    const int ld_r = tid >> 3;        // 0..63
    const int ld_c = tid & 7;         // 0..7

    auto load_stage = [&](int kit, int s) {
        if (kit < NUM_K_ITERS) {
            const uint32_t sa = base + s * STAGE_BYTES;
            const uint32_t sb = sa + A_STAGE;
            const __nv_bfloat16* ak = Ag + kit * BK + ld_c * 8;
            const __nv_bfloat16* bk = Bg + kit * BK + ld_c * 8;
#pragma unroll
            for (int it = 0; it < 2; it++) {       // A: 128 rows
                int r = ld_r + it * 64;
                cp_async16(sa + r * AST + ld_c * 16, ak + (size_t)r * KDIM);
            }
#pragma unroll
            for (int it = 0; it < 4; it++) {       // B: 256 rows
                int r = ld_r + it * 64;
                cp_async16(sb + r * AST + ld_c * 16, bk + (size_t)r * KDIM);
            }
        }
        cp_commit();
    };

    // ldmatrix x4: lane 8i+j supplies row j of matrix i.
    const int g = lane >> 3;
    const int j = lane & 7;
    const int frag_row = (g & 1) * 8 + j;           // 0..15
    const int frag_kb  = (g >> 1) * 16;             // 0 or 16 bytes

    const uint32_t a_off0 = (uint32_t)((wm0 + frag_row) * AST + frag_kb);
    const uint32_t b_off0 = (uint32_t)((wn0 + frag_row) * AST + frag_kb);

    float acc[2][8][4];                // 32x64 warp tile = 64 regs
#pragma unroll
    for (int i = 0; i < 2; i++)
#pragma unroll
        for (int n = 0; n < 8; n++)
#pragma unroll
            for (int e = 0; e < 4; e++) acc[i][n][e] = 0.0f;

    // Prologue: fill 3 of 4 stages (prefetch distance 3)
    load_stage(0, 0);
    load_stage(1, 1);
    load_stage(2, 2);

    for (int kit = 0; kit < NUM_K_ITERS; kit++) {
        const int s = kit & (STAGES - 1);
        cp_wait<2>();          // stage kit's group complete
        __syncthreads();       // single barrier per stage

        // Prefetch stage kit+3 into slot (kit-1)%4 (reads done pre-barrier)
        load_stage(kit + 3, (kit + 3) & (STAGES - 1));

        const uint32_t sa = base + s * STAGE_BYTES;
        const uint32_t sb = sa + A_STAGE;

#pragma unroll
        for (int q = 0; q < 4; q++) {              // 4 x K16 per BK=64 stage
            const uint32_t kb = (uint32_t)(q * 32);
            uint32_t a[2][4], b[4][4];
#pragma unroll
            for (int mi = 0; mi < 2; mi++)
                ldsm_x4(a[mi][0], a[mi][1], a[mi][2], a[mi][3],
                        sa + a_off0 + mi * 16 * AST + kb);
#pragma unroll
            for (int p = 0; p < 4; p++)
                ldsm_x4(b[p][0], b[p][1], b[p][2], b[p][3],
                        sb + b_off0 + p * 16 * AST + kb);
#pragma unroll
            for (int p = 0; p < 4; p++)
#pragma unroll
                for (int mi = 0; mi < 2; mi++) {
                    mma16816(acc[mi][2 * p],     a[mi], b[p][0], b[p][2]);
                    mma16816(acc[mi][2 * p + 1], a[mi], b[p][1], b[p][3]);
                }
        }
    }

    // Epilogue: value = bf16(fp32 accum) + bf16 bias, stored as fp32
#pragma unroll
    for (int mi = 0; mi < 2; mi++) {
        int r0 = m0 + wm0 + mi * 16 + (lane >> 2);
        float* p0 = out + (size_t)r0 * NDIM;
        float* p1 = p0 + (size_t)8 * NDIM;
#pragma unroll
        for (int nj = 0; nj < 8; nj++) {
            int col = n0 + wn0 + nj * 8 + (lane & 3) * 2;
            __nv_bfloat16 b0 = __float2bfloat16_rn(bias[col]);
            __nv_bfloat16 b1 = __float2bfloat16_rn(bias[col + 1]);
            float2 v0, v1;
            v0.x = __bfloat162float(__hadd(__float2bfloat16_rn(acc[mi][nj][0]), b0));
            v0.y = __bfloat162float(__hadd(__float2bfloat16_rn(acc[mi][nj][1]), b1));
            v1.x = __bfloat162float(__hadd(__float2bfloat16_rn(acc[mi][nj][2]), b0));
            v1.y = __bfloat162float(__hadd(__float2bfloat16_rn(acc[mi][nj][3]), b1));
            *reinterpret_cast<float2*>(p0 + col) = v0;
            *reinterpret_cast<float2*>(p1 + col) = v1;
        }
    }
}

// ============================================================================
// Launch
// ============================================================================
extern "C" void kernel_launch(void* const* d_in, const int* in_sizes, int n_in,
                              void* d_out, int out_size) {
    const float* x     = (const float*)d_in[0];
    const float* wq    = (const float*)d_in[1];
    const float* wscal = (const float*)d_in[2];
    const float* bias  = (const float*)d_in[3];
    float* out         = (float*)d_out;

    cudaFuncSetAttribute(gemm_kernel,
                         cudaFuncAttributeMaxDynamicSharedMemorySize,
                         SMEM_BYTES);

    cvt_kernel<<<16384, 256>>>(x, wq, wscal);
    gemm_kernel<<<NUM_M_TILES * NUM_N_TILES, THREADS, SMEM_BYTES>>>(out, bias);
}

// round 14
// speedup vs baseline: 1.0793x; 1.0130x over previous
#include <cuda_runtime.h>
#include <cuda_bf16.h>
#include <cstdint>
#include <cstddef>

// ============================================================================
// out[4096,4096](fp32, bf16-valued) = X[4096,4096](bf16) @ W[4096,4096]^T
// mma.sync.m16n8k16.bf16 (rt=16/SMSP floor), 5-stage cp.async pipeline.
// BM=BN=128 -> 1024 CTAs = 6.92 waves (tail waste ~1% vs 13.5% at BN=256).
// ============================================================================
#define MDIM 4096
#define NDIM 4096
#define KDIM 4096

#define BM 128
#define BN 128
#define BK 64                 // 64 bf16 = 128 B of K per stage row
#define STAGES 5
#define THREADS 512

#define AST 144               // padded row stride (128 data + 16 pad)
#define A_STAGE (BM * AST)                    // 18432 B
#define B_STAGE (BN * AST)                    // 18432 B
#define STAGE_BYTES (A_STAGE + B_STAGE)       // 36864 B
#define SMEM_BYTES (STAGES * STAGE_BYTES + 256)   // ~184.6 KB

#define NUM_K_ITERS (KDIM / BK)   // 64
#define NUM_M_TILES (MDIM / BM)   // 32
#define NUM_N_TILES (NDIM / BN)   // 32

__device__ __nv_bfloat16 g_xb[(size_t)MDIM * KDIM];
__device__ __nv_bfloat16 g_wb[(size_t)NDIM * KDIM];

// ============================================================================
// PTX helpers
// ============================================================================
__device__ __forceinline__ uint32_t smem_u32(const void* p) {
    uint32_t a;
    asm("{ .reg .u64 t; cvta.to.shared.u64 t, %1; cvt.u32.u64 %0, t; }"
        : "=r"(a) : "l"(p));
    return a;
}

__device__ __forceinline__ void cp_async16(uint32_t dst, const void* src) {
    asm volatile("cp.async.cg.shared.global [%0], [%1], 16;"
                 :: "r"(dst), "l"(src) : "memory");
}

__device__ __forceinline__ void cp_commit() {
    asm volatile("cp.async.commit_group;" ::: "memory");
}

template <int N>
__device__ __forceinline__ void cp_wait() {
    asm volatile("cp.async.wait_group %0;" :: "n"(N) : "memory");
}

__device__ __forceinline__ void ldsm_x4(uint32_t& r0, uint32_t& r1,
                                        uint32_t& r2, uint32_t& r3,
                                        uint32_t addr) {
    asm volatile("ldmatrix.sync.aligned.m8n8.x4.shared.b16 {%0,%1,%2,%3}, [%4];"
                 : "=r"(r0), "=r"(r1), "=r"(r2), "=r"(r3) : "r"(addr));
}

__device__ __forceinline__ void mma16816(float* c, const uint32_t* a,
                                         uint32_t b0, uint32_t b1) {
    asm volatile(
        "mma.sync.aligned.m16n8k16.row.col.f32.bf16.bf16.f32 "
        "{%0,%1,%2,%3}, {%4,%5,%6,%7}, {%8,%9}, {%0,%1,%2,%3};"
        : "+f"(c[0]), "+f"(c[1]), "+f"(c[2]), "+f"(c[3])
        : "r"(a[0]), "r"(a[1]), "r"(a[2]), "r"(a[3]), "r"(b0), "r"(b1));
}

__device__ __forceinline__ unsigned pack2(__nv_bfloat16 lo, __nv_bfloat16 hi) {
    return (unsigned)__bfloat16_as_ushort(lo) |
           ((unsigned)__bfloat16_as_ushort(hi) << 16);
}

// ============================================================================
// Fused convert: blocks [0,8192) cast X; [8192,16384) dequant W (bf16 math)
// ============================================================================
__global__ __launch_bounds__(256) void cvt_kernel(const float* __restrict__ x,
                                                  const float* __restrict__ w,
                                                  const float* __restrict__ scale) {
    if (blockIdx.x < 8192) {
        size_t i = (size_t)blockIdx.x * 256 + threadIdx.x;      // 8 floats
        const float4* p = reinterpret_cast<const float4*>(x) + i * 2;
        float4 a = p[0], b = p[1];
        uint4 o;
        o.x = pack2(__float2bfloat16_rn(a.x), __float2bfloat16_rn(a.y));
        o.y = pack2(__float2bfloat16_rn(a.z), __float2bfloat16_rn(a.w));
        o.z = pack2(__float2bfloat16_rn(b.x), __float2bfloat16_rn(b.y));
        o.w = pack2(__float2bfloat16_rn(b.z), __float2bfloat16_rn(b.w));
        reinterpret_cast<uint4*>(g_xb)[i] = o;
    } else {
        size_t i = (size_t)(blockIdx.x - 8192) * 256 + threadIdx.x;
        int row = (int)(i >> 9);
        __nv_bfloat16 sb = __float2bfloat16_rn(scale[row]);
        const float4* p = reinterpret_cast<const float4*>(w) + i * 2;
        float4 a = p[0], b = p[1];
        float f[8] = {a.x, a.y, a.z, a.w, b.x, b.y, b.z, b.w};
        unsigned u[4];
#pragma unroll
        for (int j = 0; j < 4; j++) {
            __nv_bfloat16 lo = __hmul(__float2bfloat16_rn(f[2 * j]), sb);
            __nv_bfloat16 hi = __hmul(__float2bfloat16_rn(f[2 * j + 1]), sb);
            u[j] = pack2(lo, hi);
        }
        reinterpret_cast<uint4*>(g_wb)[i] = make_uint4(u[0], u[1], u[2], u[3]);
    }
}

// ============================================================================
// GEMM: 128x128x64 CTA tile, 16 warps @ 32x32, 5-stage pipeline, 1 bar/stage
// ============================================================================
__global__ __launch_bounds__(THREADS, 1) void gemm_kernel(
    float* __restrict__ out, const float* __restrict__ bias) {
    extern __shared__ char smem[];
    const uint32_t base = (smem_u32(smem) + 127u) & ~127u;

    const int tid = threadIdx.x;
    const int lane = tid & 31;
    const int wid = tid >> 5;
    const int wm0 = (wid & 3) * 32;    // 4 warp rows * 32 = 128
    const int wn0 = (wid >> 2) * 32;   // 4 warp cols * 32 = 128

    const int bid = blockIdx.x;
    const int tm = bid & (NUM_M_TILES - 1);  // consecutive bids share B panel
    const int tn = bid >> 5;
    const int m0 = tm * BM;
    const int n0 = tn * BN;

    const __nv_bfloat16* Ag = g_xb + (size_t)m0 * KDIM;
    const __nv_bfloat16* Bg = g_wb + (size_t)n0 * KDIM;

    // cp.async: 512 threads; A+B = 2048 16B chunks per stage -> 4/thread
    const int ld_r = tid >> 3;        // 0..63
    const int ld_c = tid & 7;         // 0..7

    auto load_stage = [&](int kit, int s) {
        if (kit < NUM_K_ITERS) {
            const uint32_t sa = base + s * STAGE_BYTES;
            const uint32_t sb = sa + A_STAGE;
            const __nv_bfloat16* ak = Ag + kit * BK + ld_c * 8;
            const __nv_bfloat16* bk = Bg + kit * BK + ld_c * 8;
#pragma unroll
            for (int it = 0; it < 2; it++) {       // A: 128 rows
                int r = ld_r + it * 64;
                cp_async16(sa + r * AST + ld_c * 16, ak + (size_t)r * KDIM);
            }
#pragma unroll
            for (int it = 0; it < 2; it++) {       // B: 128 rows
                int r = ld_r + it * 64;
                cp_async16(sb + r * AST + ld_c * 16, bk + (size_t)r * KDIM);
            }
        }
        cp_commit();
    };

    // ldmatrix x4: lane 8i+j supplies row j of matrix i.
    const int g = lane >> 3;
    const int j = lane & 7;
    const int frag_row = (g & 1) * 8 + j;           // 0..15
    const int frag_kb  = (g >> 1) * 16;             // 0 or 16 bytes

    const uint32_t a_off0 = (uint32_t)((wm0 + frag_row) * AST + frag_kb);
    const uint32_t b_off0 = (uint32_t)((wn0 + frag_row) * AST + frag_kb);

    float acc[2][4][4];                // 32x32 warp tile = 32 regs
#pragma unroll
    for (int i = 0; i < 2; i++)
#pragma unroll
        for (int n = 0; n < 4; n++)
#pragma unroll
            for (int e = 0; e < 4; e++) acc[i][n][e] = 0.0f;

    // Prologue: fill STAGES-1 = 4 stages (prefetch distance 4)
    load_stage(0, 0);
    load_stage(1, 1);
    load_stage(2, 2);
    load_stage(3, 3);

    for (int kit = 0; kit < NUM_K_ITERS; kit++) {
        const int s = kit % STAGES;
        cp_wait<3>();          // group kit complete (4 newer may be in flight)
        __syncthreads();       // single barrier per stage

        // Prefetch stage kit+4 into slot (kit+4)%5 = (kit-1)%5, whose reads
        // finished during iteration kit-1 (before this barrier).
        load_stage(kit + 4, (kit + 4) % STAGES);

        const uint32_t sa = base + s * STAGE_BYTES;
        const uint32_t sb = sa + A_STAGE;

#pragma unroll
        for (int q = 0; q < 4; q++) {              // 4 x K16 per BK=64 stage
            const uint32_t kb = (uint32_t)(q * 32);
            uint32_t a[2][4], b[2][4];
#pragma unroll
            for (int mi = 0; mi < 2; mi++)
                ldsm_x4(a[mi][0], a[mi][1], a[mi][2], a[mi][3],
                        sa + a_off0 + mi * 16 * AST + kb);
#pragma unroll
            for (int p = 0; p < 2; p++)
                ldsm_x4(b[p][0], b[p][1], b[p][2], b[p][3],
                        sb + b_off0 + p * 16 * AST + kb);
#pragma unroll
            for (int p = 0; p < 2; p++)
#pragma unroll
                for (int mi = 0; mi < 2; mi++) {
                    mma16816(acc[mi][2 * p],     a[mi], b[p][0], b[p][2]);
                    mma16816(acc[mi][2 * p + 1], a[mi], b[p][1], b[p][3]);
                }
        }
    }

    // Epilogue: value = bf16(fp32 accum) + bf16 bias, stored as fp32
#pragma unroll
    for (int mi = 0; mi < 2; mi++) {
        int r0 = m0 + wm0 + mi * 16 + (lane >> 2);
        float* p0 = out + (size_t)r0 * NDIM;
        float* p1 = p0 + (size_t)8 * NDIM;
#pragma unroll
        for (int nj = 0; nj < 4; nj++) {
            int col = n0 + wn0 + nj * 8 + (lane & 3) * 2;
            __nv_bfloat16 b0 = __float2bfloat16_rn(bias[col]);
            __nv_bfloat16 b1 = __float2bfloat16_rn(bias[col + 1]);
            float2 v0, v1;
            v0.x = __bfloat162float(__hadd(__float2bfloat16_rn(acc[mi][nj][0]), b0));
            v0.y = __bfloat162float(__hadd(__float2bfloat16_rn(acc[mi][nj][1]), b1));
            v1.x = __bfloat162float(__hadd(__float2bfloat16_rn(acc[mi][nj][2]), b0));
            v1.y = __bfloat162float(__hadd(__float2bfloat16_rn(acc[mi][nj][3]), b1));
            *reinterpret_cast<float2*>(p0 + col) = v0;
            *reinterpret_cast<float2*>(p1 + col) = v1;
        }
    }
}

// ============================================================================
// Launch
// ============================================================================
extern "C" void kernel_launch(void* const* d_in, const int* in_sizes, int n_in,
                              void* d_out, int out_size) {
    const float* x     = (const float*)d_in[0];
    const float* wq    = (const float*)d_in[1];
    const float* wscal = (const float*)d_in[2];
    const float* bias  = (const float*)d_in[3];
    float* out         = (float*)d_out;

    cudaFuncSetAttribute(gemm_kernel,
                         cudaFuncAttributeMaxDynamicSharedMemorySize,
                         SMEM_BYTES);

    cvt_kernel<<<16384, 256>>>(x, wq, wscal);
    gemm_kernel<<<NUM_M_TILES * NUM_N_TILES, THREADS, SMEM_BYTES>>>(out, bias);
}